// round 2
// baseline (speedup 1.0000x reference)
#include <cuda_runtime.h>
#include <cstdint>

#define BATCH    512
#define BITD     64
#define NCLS     100
#define NTRAIN   100000
#define MARGIN_F 128.0f

#define SCAN_BLOCKS 391          // ceil(100000/256)
#define UST_BLOCKS  160
#define FIX_BLOCKS  2
#define TOTAL_BLOCKS (SCAN_BLOCKS + UST_BLOCKS + FIX_BLOCKS)

// -------- device accumulators / scratch (no allocations allowed) --------
__device__ double   g_sum_usq;        // sum_b |u_b|^2
__device__ double   g_s2;             // sum |1 - sign(u)|
__device__ double   g_SUsq;           // sum_n |U'_n|^2 (after update)
__device__ double   g_corr;           // hinge correction over mismatch pairs
__device__ double   g_su[BITD];       // column sums of u
__device__ double   g_SU[BITD];       // column sums of U' (after update)
__device__ float    g_usq[BATCH];     // per-row |u_b|^2
__device__ unsigned g_ypk[4 * BATCH]; // packed batch labels, word-major [w][b]
__device__ unsigned g_done;           // block completion counter

__device__ __forceinline__ float wred(float v) {
#pragma unroll
    for (int o = 16; o; o >>= 1) v += __shfl_xor_sync(0xffffffffu, v, o);
    return v;
}

// --------- rare path: exact pair term 0.5*(max(m-d,0) - d) --------------
// MUST be the single definition used by scan (add) and fix (subtract) so the
// old-term cancellation is bit-exact.
__device__ __noinline__ double pair_term(int b, const float* __restrict__ ur,
                                         const float* __restrict__ vr) {
    float dot = 0.f, vsq = 0.f;
#pragma unroll 16
    for (int k = 0; k < BITD; k++) {
        float a = ur[k], c = vr[k];
        dot = fmaf(a, c, dot);
        vsq = fmaf(c, c, vsq);
    }
    float d = g_usq[b] - 2.f * dot + vsq;
    d = fmaxf(d, 0.f);
    return 0.5 * ((double)fmaxf(MARGIN_F - d, 0.f) - (double)d);
}

// ------------------------------------------------- batch stats + y pack
__global__ void k_batch(const float* __restrict__ u,
                        const float* __restrict__ y) {
    __shared__ float ssu[BITD];
    __shared__ float swq[16], sws[16];
    int i    = threadIdx.x;            // 512 threads, 1 block
    int lane = i & 31, warp = i >> 5;

    // zero everything k_main accumulates into
    if (i < BITD) { ssu[i] = 0.f; g_SU[i] = 0.0; }
    if (i == 0) { g_SUsq = 0.0; g_corr = 0.0; g_done = 0u; }
    __syncthreads();

    const float* ur = u + i * BITD;
    float usq = 0.f, s2 = 0.f;
#pragma unroll
    for (int kk = 0; kk < BITD; kk++) {
        int k = (kk + i) & (BITD - 1);     // staggered: conflict-free in warp
        float v = ur[k];
        usq += v * v;
        s2  += (v > 0.f) ? 0.f : ((v < 0.f) ? 2.f : 1.f);
        atomicAdd(&ssu[k], v);
    }
    g_usq[i] = usq;
    float ru = wred(usq), rs = wred(s2);
    if (lane == 0) { swq[warp] = ru; sws[warp] = rs; }

    // pack this thread's y row into 4 words (bit c set iff y[c] != 0)
    const float* yr = y + (size_t)i * NCLS;
    unsigned w0 = 0, w1 = 0, w2 = 0, w3 = 0;
#pragma unroll
    for (int c = 0; c < 32; c++) {
        if (yr[c]      != 0.f) w0 |= 1u << c;
        if (yr[32 + c] != 0.f) w1 |= 1u << c;
        if (yr[64 + c] != 0.f) w2 |= 1u << c;
    }
#pragma unroll
    for (int c = 0; c < 4; c++)
        if (yr[96 + c] != 0.f) w3 |= 1u << c;
    g_ypk[i]             = w0;
    g_ypk[BATCH + i]     = w1;
    g_ypk[2 * BATCH + i] = w2;
    g_ypk[3 * BATCH + i] = w3;

    __syncthreads();
    if (i < BITD) g_su[i] = (double)ssu[i];
    if (i == 0) {
        float a = 0.f, b = 0.f;
#pragma unroll
        for (int w = 0; w < 16; w++) { a += swq[w]; b += sws[w]; }
        g_sum_usq = (double)a;
        g_s2      = (double)b;
    }
}

// ------------- fused kernel: scan + U stats + buffer-update fix + finalize
__global__ void __launch_bounds__(256)
k_main(const float* __restrict__ u, const float* __restrict__ y,
       const int* __restrict__ ind,
       const float* __restrict__ U, const float* __restrict__ Y,
       float* __restrict__ out) {
    __shared__ unsigned sh[4 * BATCH];   // 8KB packed labels (roles reuse)
    __shared__ int      sind[BATCH];
    __shared__ float    scol[BITD];

    int t    = threadIdx.x;
    int lane = t & 31, warp = t >> 5;

    if (blockIdx.x < SCAN_BLOCKS) {
        // ================= scan role: original Y vs batch packs ==========
        for (int i = t; i < BATCH; i += 256) {
            sh[i]             = g_ypk[i];
            sh[BATCH + i]     = g_ypk[BATCH + i];
            sh[2 * BATCH + i] = g_ypk[2 * BATCH + i];
            sh[3 * BATCH + i] = g_ypk[3 * BATCH + i];
        }

        int n     = blockIdx.x * 256 + t;
        int nbase = blockIdx.x * 256 + warp * 32;

        // warp-cooperative pack of 32 training rows via ballot
        unsigned w0 = 0, w1 = 0, w2 = 0, w3 = 0;
        for (int r = 0; r < 32; r++) {
            int nr = nbase + r;
            size_t off = (size_t)((nr < NTRAIN) ? nr : 0) * NCLS;
            const float* src = Y + off;
            float v0 = src[lane];
            float v1 = src[32 + lane];
            float v2 = src[64 + lane];
            float v3 = (lane < 4) ? src[96 + lane] : 0.f;
            unsigned b0 = __ballot_sync(0xffffffffu, v0 != 0.f);
            unsigned b1 = __ballot_sync(0xffffffffu, v1 != 0.f);
            unsigned b2 = __ballot_sync(0xffffffffu, v2 != 0.f);
            unsigned b3 = __ballot_sync(0xffffffffu, v3 != 0.f);
            if (lane == r) { w0 = b0; w1 = b1; w2 = b2; w3 = b3; }
        }
        __syncthreads();

        if (n < NTRAIN) {
            double corr = 0.0;
#pragma unroll 4
            for (int b0i = 0; b0i < BATCH; b0i += 8) {
                unsigned mna = sh[b0i]     & w0;
                unsigned mnb = sh[b0i + 4] & w0;
#pragma unroll
                for (int j = 1; j < 4; j++) {
                    mna = min(mna, sh[b0i + j]     & w0);
                    mnb = min(mnb, sh[b0i + 4 + j] & w0);
                }
                if (min(mna, mnb) == 0u) {
#pragma unroll 1
                    for (int j = 0; j < 8; j++) {
                        int b = b0i + j;
                        unsigned r = (sh[b] & w0) | (sh[BATCH + b] & w1) |
                                     (sh[2 * BATCH + b] & w2) |
                                     (sh[3 * BATCH + b] & w3);
                        if (r == 0u)
                            corr += pair_term(b, u + b * BITD,
                                              U + (size_t)n * BITD);
                    }
                }
            }
            if (corr != 0.0) atomicAdd(&g_corr, corr);
        }
    } else if (blockIdx.x < SCAN_BLOCKS + UST_BLOCKS) {
        // ================= U stats role (original U) =====================
        int lwarp = (blockIdx.x - SCAN_BLOCKS) * 8 + warp;
        const int totw = UST_BLOCKS * 8;
        float c0 = 0.f, c1 = 0.f, sq = 0.f;
        for (int n = lwarp; n < NTRAIN; n += totw) {
            float2 v = *(const float2*)(U + (size_t)n * BITD + lane * 2);
            c0 += v.x; c1 += v.y;
            sq += v.x * v.x + v.y * v.y;
        }
        sq = wred(sq);

        float* sc  = (float*)sh;
        float* sws = ((float*)sh) + 64;
        if (t < 72) sc[t] = 0.f;
        __syncthreads();
        atomicAdd(&sc[lane * 2],     c0);
        atomicAdd(&sc[lane * 2 + 1], c1);
        if (lane == 0) sws[warp] = sq;
        __syncthreads();
        if (t < BITD) atomicAdd(&g_SU[t], (double)sc[t]);
        if (t == 0) {
            float s = 0.f;
#pragma unroll
            for (int w = 0; w < 8; w++) s += sws[w];
            atomicAdd(&g_SUsq, (double)s);
        }
    } else {
        // ================= fix role: buffer updates ======================
        int rb = blockIdx.x - SCAN_BLOCKS - UST_BLOCKS;   // 0..1
        for (int j = t; j < BATCH; j += 256) sind[j] = ind[j];
        for (int j = t; j < 4 * BATCH; j += 256) sh[j] = g_ypk[j];
        if (t < BITD) scol[t] = 0.f;
        __syncthreads();

        int  i = rb * 256 + t;
        int  n = sind[i];
        bool last = true;
        for (int j = i + 1; j < BATCH; j++)
            if (sind[j] == n) { last = false; break; }

        double corr = 0.0; float dsq = 0.f;
        if (last) {
            unsigned m0 = sh[i],             m1 = sh[BATCH + i];
            unsigned m2 = sh[2 * BATCH + i], m3 = sh[3 * BATCH + i];
            // pack original Y row n
            const float* yr = Y + (size_t)n * NCLS;
            unsigned yn0 = 0, yn1 = 0, yn2 = 0, yn3 = 0;
#pragma unroll
            for (int c = 0; c < 32; c++) {
                if (yr[c]      != 0.f) yn0 |= 1u << c;
                if (yr[32 + c] != 0.f) yn1 |= 1u << c;
                if (yr[64 + c] != 0.f) yn2 |= 1u << c;
            }
#pragma unroll
            for (int c = 0; c < 4; c++)
                if (yr[96 + c] != 0.f) yn3 |= 1u << c;

            for (int b0i = 0; b0i < BATCH; b0i += 8) {
                unsigned mo = sh[b0i] & yn0;
                unsigned mn = sh[b0i] & m0;
#pragma unroll
                for (int j = 1; j < 8; j++) {
                    mo = min(mo, sh[b0i + j] & yn0);
                    mn = min(mn, sh[b0i + j] & m0);
                }
                if (min(mo, mn) == 0u) {
#pragma unroll 1
                    for (int j = 0; j < 8; j++) {
                        int b = b0i + j;
                        unsigned ro = (sh[b] & yn0) | (sh[BATCH + b] & yn1) |
                                      (sh[2 * BATCH + b] & yn2) |
                                      (sh[3 * BATCH + b] & yn3);
                        if (ro == 0u)   // remove scan's old-data contribution
                            corr -= pair_term(b, u + b * BITD,
                                              U + (size_t)n * BITD);
                        unsigned rn = (sh[b] & m0) | (sh[BATCH + b] & m1) |
                                      (sh[2 * BATCH + b] & m2) |
                                      (sh[3 * BATCH + b] & m3);
                        if (rn == 0u)   // add updated-data contribution
                            corr += pair_term(b, u + b * BITD, u + i * BITD);
                    }
                }
            }
            // SU / SUsq delta for the overwritten row
            const float* ur = u + i * BITD;
            const float* Ur = U + (size_t)n * BITD;
#pragma unroll
            for (int kk = 0; kk < BITD; kk++) {
                int k = (kk + t) & (BITD - 1);
                float a = ur[k], c = Ur[k];
                dsq += a * a - c * c;
                atomicAdd(&scol[k], a - c);
            }
        }
        if (corr != 0.0) atomicAdd(&g_corr, corr);
        dsq = wred(dsq);
        if (lane == 0 && dsq != 0.f) atomicAdd(&g_SUsq, (double)dsq);
        __syncthreads();
        if (t < BITD && scol[t] != 0.f) atomicAdd(&g_SU[t], (double)scol[t]);
    }

    // ================= last block finalizes =============================
    __syncthreads();
    __threadfence();
    if (t == 0) {
        if (atomicAdd(&g_done, 1u) == TOTAL_BLOCKS - 1) {
            __threadfence();
            double dotsum = 0.0;
#pragma unroll
            for (int k = 0; k < BITD; k++) dotsum += g_su[k] * g_SU[k];
            double sum_dist = (double)NTRAIN * g_sum_usq
                            + (double)BATCH  * g_SUsq
                            - 2.0 * dotsum;
            double loss1 = (0.5 * sum_dist + g_corr)
                         / ((double)BATCH * (double)NTRAIN);
            double loss2 = 0.1 * g_s2 / ((double)BATCH * (double)BITD);
            out[0] = (float)(loss1 + loss2);
        }
    }
}

// ------------------------------------------------------------ launcher
extern "C" void kernel_launch(void* const* d_in, const int* in_sizes, int n_in,
                              void* d_out, int out_size) {
    const float* u   = (const float*)d_in[0];   // [512, 64]
    const float* y   = (const float*)d_in[1];   // [512, 100]
    const int*   ind = (const int*)  d_in[2];   // [512]
    const float* U   = (const float*)d_in[3];   // [100000, 64]
    const float* Y   = (const float*)d_in[4];   // [100000, 100]
    float* out = (float*)d_out;

    k_batch<<<1, BATCH>>>(u, y);
    k_main<<<TOTAL_BLOCKS, 256>>>(u, y, ind, U, Y, out);
}